// round 10
// baseline (speedup 1.0000x reference)
#include <cuda_runtime.h>
#include <cstdint>

// Problem constants
#define NB    1024
#define NTCR  100
#define NFEAT 15
#define NAA   24
#define NCH   14          // total conv output channels
#define NINST (NB*NTCR)   // 102400
#define INST_PER_BLOCK 32
#define NBLK_CONV (NINST/INST_PER_BLOCK) // 3200
#define CONV_THREADS 224  // 7 warps: warp = channel pair, lane = instance
#define NWPACK 1484       // 1470 weights (layout [c][ch*7+t]) + 14 biases

// ---------------- scratch (static device memory; no allocation) ----------------
__device__ float g_hbuf[NINST * NCH];   // h vectors (per instance)
__device__ float g_sbuf[NINST];         // attention scores
__device__ float g_zbuf[NB * NCH];      // decoder_f output (pre-BN)
__device__ float g_wpack[NWPACK];       // staged conv weights+bias

// Diagnostic: keeps convKernel at ncu's captured launch index (-s 5 -c 1).
__global__ void dummyKernel() {}

// ---------------- prep: pack conv weights, layout [c][ch*7 + t] ----------------
__global__ void prepKernel(const float* __restrict__ w0, const float* __restrict__ b0,
                           const float* __restrict__ w1, const float* __restrict__ b1,
                           const float* __restrict__ w2, const float* __restrict__ b2,
                           const float* __restrict__ w3, const float* __restrict__ b3,
                           const float* __restrict__ w4, const float* __restrict__ b4,
                           const float* __restrict__ w5, const float* __restrict__ b5) {
    const int chH[14]    = {2,2,2,3,3,3,4,4,4,5,5,6,6,7};
    const int chF[14]    = {0,1,2,0,1,2,0,1,2,0,1,0,1,0};
    const int chConv[14] = {0,0,0,1,1,1,2,2,2,3,3,4,4,5};
    const float* cws[6] = {w0,w1,w2,w3,w4,w5};
    const float* cbs[6] = {b0,b1,b2,b3,b4,b5};
    int idx = blockIdx.x * blockDim.x + threadIdx.x;
    if (idx < 1470) {
        int c  = idx / 98;
        int r  = idx - c * 98;
        int ch = r / 7;
        int t  = r - ch * 7;
        int h  = chH[ch];
        float w = 0.0f;
        if (t < h) {
            const float* W = cws[chConv[ch]];
            w = W[(chF[ch] * NFEAT + c) * h + t];
        }
        g_wpack[idx] = w;
    } else if (idx < NWPACK) {
        int ch = idx - 1470;
        g_wpack[idx] = cbs[chConv[ch]][chF[ch]];
    }
}

// ---------------- conv body: compile-time tap heights, zero wasted FFMAs ----------------
// lane = instance; this warp computes channels chA (height H1) and chB (H2)
// for all 32 instances. acc arrays hold EXACTLY the valid output positions.
template<int H1, int H2>
__device__ __forceinline__ void convBody(const float* __restrict__ x, int instBase,
                                         int tid, int lane, int chA, int chB,
                                         float (*xsm)[INST_PER_BLOCK][25],
                                         const float* __restrict__ wsm,
                                         float& fA, float& fB) {
    float accA[25 - H1];
    float accB[25 - H2];
    #pragma unroll
    for (int p = 0; p <= 24 - H1; ++p) accA[p] = 0.0f;
    #pragma unroll
    for (int p = 0; p <= 24 - H2; ++p) accB[p] = 0.0f;

    #pragma unroll 1
    for (int c = 0; c < 15; ++c) {
        // cooperative staging of row c+1 into the other buffer (all warps)
        if (c < 14) {
            for (int e = tid; e < INST_PER_BLOCK * 24; e += CONV_THREADS) {
                int inst = e / 24;
                int i    = e - inst * 24;
                xsm[(c + 1) & 1][inst][i] =
                    x[(size_t)(instBase + inst) * 360 + (c + 1) * 24 + i];
            }
        }

        // x row for this lane's instance (stride 25 -> conflict-free LDS)
        const float* xr = xsm[c & 1][lane];
        float xv[24];
        #pragma unroll
        for (int a = 0; a < 24; ++a) xv[a] = xr[a];

        const float* wrA = wsm + c * 98 + chA * 7;
        #pragma unroll
        for (int t = 0; t < H1; ++t) {
            float wv = wrA[t];
            #pragma unroll
            for (int p = 0; p <= 24 - H1; ++p)
                accA[p] = fmaf(wv, xv[p + t], accA[p]);
        }
        const float* wrB = wsm + c * 98 + chB * 7;
        #pragma unroll
        for (int t = 0; t < H2; ++t) {
            float wv = wrB[t];
            #pragma unroll
            for (int p = 0; p <= 24 - H2; ++p)
                accB[p] = fmaf(wv, xv[p + t], accB[p]);
        }
        __syncthreads();
    }

    float mA = accA[0];
    #pragma unroll
    for (int p = 1; p <= 24 - H1; ++p) mA = fmaxf(mA, accA[p]);
    float mB = accB[0];
    #pragma unroll
    for (int p = 1; p <= 24 - H2; ++p) mB = fmaxf(mB, accB[p]);
    fA = mA;
    fB = mB;
}

// ---------------- stage 1: conv + relu + maxpool + fc1 + relu + score ----------------
__global__ void __launch_bounds__(CONV_THREADS, 3) convKernel(const float* __restrict__ x,
                                                              const float* __restrict__ fc1w,
                                                              const float* __restrict__ fc1b,
                                                              const float* __restrict__ waw) {
    __shared__ float xsm[2][INST_PER_BLOCK][25]; // double-buffered x row tiles
    __shared__ float wsm[1470];                  // [c][ch*7+t]
    __shared__ float fcw[224];                   // 16x14 zero-padded
    __shared__ float fcb[16];
    __shared__ float wav[16];
    __shared__ float wbias[16];
    __shared__ float feats[INST_PER_BLOCK][16];
    __shared__ float scs[INST_PER_BLOCK][14];

    int tid  = threadIdx.x;
    int w    = tid >> 5;      // 0..6 = channel pair
    int lane = tid & 31;      // instance within block
    int instBase = blockIdx.x * INST_PER_BLOCK;

    for (int i = tid; i < 1470; i += CONV_THREADS) wsm[i] = g_wpack[i];
    fcw[tid < 224 ? tid : 0] = 0.0f; // (224 threads cover 224 entries exactly)
    fcw[tid] = (tid < 196) ? fc1w[tid] : 0.0f;
    if (tid < 16) {
        fcb[tid]   = (tid < 14) ? fc1b[tid] : 0.0f;
        wav[tid]   = (tid < 14) ? waw[tid]  : 0.0f;
        wbias[tid] = (tid < 14) ? g_wpack[1470 + tid] : 0.0f;
    }

    // prologue: stage x row 0
    for (int e = tid; e < INST_PER_BLOCK * 24; e += CONV_THREADS) {
        int inst = e / 24;
        int i    = e - inst * 24;
        xsm[0][inst][i] = x[(size_t)(instBase + inst) * 360 + i];
    }
    __syncthreads();

    // channel pairing, height-balanced: (7,2),(6,2),(6,2),(5,3),(5,3),(4,3),(4,4)
    const int pA[7] = {13, 11, 12,  9, 10,  6,  7};
    const int pB[7] = { 0,  1,  2,  3,  4,  5,  8};
    int chA = pA[w], chB = pB[w];

    float fA, fB;
    switch (w) {
        case 0:          convBody<7,2>(x, instBase, tid, lane, chA, chB, xsm, wsm, fA, fB); break;
        case 1: case 2:  convBody<6,2>(x, instBase, tid, lane, chA, chB, xsm, wsm, fA, fB); break;
        case 3: case 4:  convBody<5,3>(x, instBase, tid, lane, chA, chB, xsm, wsm, fA, fB); break;
        case 5:          convBody<4,3>(x, instBase, tid, lane, chA, chB, xsm, wsm, fA, fB); break;
        default:         convBody<4,4>(x, instBase, tid, lane, chA, chB, xsm, wsm, fA, fB); break;
    }

    feats[lane][chA] = fmaxf(fA + wbias[chA], 0.0f);
    feats[lane][chB] = fmaxf(fB + wbias[chB], 0.0f);
    __syncthreads();

    // fc1 + relu + per-(inst,j) score term
    for (int u = tid; u < INST_PER_BLOCK * 14; u += CONV_THREADS) {
        int inst = u / 14;
        int j    = u - inst * 14;
        float hv = fcb[j];
        #pragma unroll
        for (int k = 0; k < 14; ++k)
            hv = fmaf(fcw[j * 14 + k], feats[inst][k], hv);
        hv = fmaxf(hv, 0.0f);
        g_hbuf[(size_t)(instBase + inst) * 14 + j] = hv;
        scs[inst][j] = hv * wav[j];
    }
    __syncthreads();

    if (tid < INST_PER_BLOCK) {
        float s = 0.0f;
        #pragma unroll
        for (int j = 0; j < 14; ++j) s += scs[tid][j];
        g_sbuf[instBase + tid] = s;
    }
}

// ---------------- stage 2: sparsemax + pooled + decoder_f (one block per repertoire) ----------------
__global__ void __launch_bounds__(128) attnKernel(const float* __restrict__ decfw,
                                                  const float* __restrict__ decfb,
                                                  float* __restrict__ out,
                                                  int write_attw) {
    __shared__ float z[100];
    __shared__ float zsrt[100];
    __shared__ float csh[100];
    __shared__ float aw[100];
    __shared__ float hsh[1400];
    __shared__ float pooled[14];
    __shared__ int   ks_sh;

    int b = blockIdx.x;
    int t = threadIdx.x;

    if (t == 0) ks_sh = 1;
    if (t < 100) z[t] = g_sbuf[b * 100 + t];
    for (int i = t; i < 1400; i += 128) hsh[i] = g_hbuf[b * 1400 + i];
    __syncthreads();

    // exact O(n^2) rank sort (descending, stable)
    if (t < 100) {
        float zi = z[t];
        int r = 0;
        for (int j2 = 0; j2 < 100; ++j2) {
            float zj = z[j2];
            r += (int)(zj > zi) | ((int)(zj == zi) & (int)(j2 < t));
        }
        zsrt[r] = zi;
    }
    __syncthreads();

    // parallel cumsum (triangular) + support-size via atomicMax
    if (t < 100) {
        float cs = 0.0f;
        for (int i2 = 0; i2 <= t; ++i2) cs += zsrt[i2];
        csh[t] = cs;
        if (1.0f + (float)(t + 1) * zsrt[t] > cs) atomicMax(&ks_sh, t + 1);
    }
    __syncthreads();

    int   ks  = ks_sh;
    float tau = (csh[ks - 1] - 1.0f) / (float)ks;

    if (t < 100) {
        float a = fmaxf(z[t] - tau, 0.0f);
        aw[t] = a;
        if (write_attw) out[2048 + b * 100 + t] = a;
    }
    __syncthreads();

    if (t < 14) {
        float acc = 0.0f;
        #pragma unroll 4
        for (int p = 0; p < 100; ++p)
            acc = fmaf(aw[p], hsh[p * 14 + t], acc);
        pooled[t] = acc;
    }
    __syncthreads();

    if (t < 14) {
        float zz = decfb[t];
        #pragma unroll
        for (int k = 0; k < 14; ++k) zz = fmaf(decfw[t * 14 + k], pooled[k], zz);
        g_zbuf[b * 14 + t] = zz;
    }
}

// ---------------- stage 3: batchnorm (batch stats) + relu + decoder_s ----------------
__global__ void __launch_bounds__(1024) bnKernel(const float* __restrict__ bng,
                                                 const float* __restrict__ bnb,
                                                 const float* __restrict__ dsw,
                                                 const float* __restrict__ dsb,
                                                 float* __restrict__ out) {
    __shared__ float ssum[32][14];
    __shared__ float ssq[32][14];
    __shared__ float mu[14];
    __shared__ float sc[14];

    int b    = threadIdx.x;
    int w    = b >> 5;
    int lane = b & 31;

    float zr[14];
    #pragma unroll
    for (int j = 0; j < 14; ++j) zr[j] = g_zbuf[b * 14 + j];

    #pragma unroll
    for (int j = 0; j < 14; ++j) {
        float s = zr[j];
        float q = zr[j] * zr[j];
        #pragma unroll
        for (int off = 16; off; off >>= 1) {
            s += __shfl_xor_sync(0xffffffffu, s, off);
            q += __shfl_xor_sync(0xffffffffu, q, off);
        }
        if (lane == 0) { ssum[w][j] = s; ssq[w][j] = q; }
    }
    __syncthreads();

    if (b < 14) {
        float s = 0.0f, q = 0.0f;
        #pragma unroll
        for (int i = 0; i < 32; ++i) { s += ssum[i][b]; q += ssq[i][b]; }
        float m = s * (1.0f / 1024.0f);
        float v = q * (1.0f / 1024.0f) - m * m;
        mu[b] = m;
        sc[b] = bng[b] * rsqrtf(v + 1e-5f);
    }
    __syncthreads();

    float l0 = dsb[0], l1 = dsb[1];
    #pragma unroll
    for (int j = 0; j < 14; ++j) {
        float zn = fmaxf((zr[j] - mu[j]) * sc[j] + bnb[j], 0.0f);
        l0 = fmaf(dsw[j],      zn, l0);
        l1 = fmaf(dsw[14 + j], zn, l1);
    }
    out[b * 2]     = l0;
    out[b * 2 + 1] = l1;
}

// ---------------- launch ----------------
extern "C" void kernel_launch(void* const* d_in, const int* in_sizes, int n_in,
                              void* d_out, int out_size) {
    static const int MAP_INS[22] = {0,1,2,3,4,5,6,7,8,9,10,11,12,13,14,15,16,17,18,19,20,21};
    //                       x  cw0 cb0 cw1 cb1 cw2 cb2 cw3 cb3 cw4 cb4 cw5 cb5 f1w f1b waw dfw dfb bng bnb dsw dsb
    static const int MAP_AL[22] = {21, 8,  2,  9,  3, 10,  4, 11,  5, 12,  6, 13,  7, 19, 18, 20, 15, 14,  1,  0, 17, 16};

    const int* M = MAP_INS;
    if (n_in >= 22 && in_sizes[0] != NINST * NFEAT * NAA && in_sizes[21] == NINST * NFEAT * NAA) {
        M = MAP_AL;
    }

    const float* x    = (const float*)d_in[M[0]];
    const float* cw0  = (const float*)d_in[M[1]];
    const float* cb0  = (const float*)d_in[M[2]];
    const float* cw1  = (const float*)d_in[M[3]];
    const float* cb1  = (const float*)d_in[M[4]];
    const float* cw2  = (const float*)d_in[M[5]];
    const float* cb2  = (const float*)d_in[M[6]];
    const float* cw3  = (const float*)d_in[M[7]];
    const float* cb3  = (const float*)d_in[M[8]];
    const float* cw4  = (const float*)d_in[M[9]];
    const float* cb4  = (const float*)d_in[M[10]];
    const float* cw5  = (const float*)d_in[M[11]];
    const float* cb5  = (const float*)d_in[M[12]];
    const float* fc1w = (const float*)d_in[M[13]];
    const float* fc1b = (const float*)d_in[M[14]];
    const float* waw  = (const float*)d_in[M[15]];
    const float* dfw  = (const float*)d_in[M[16]];
    const float* dfb  = (const float*)d_in[M[17]];
    const float* bng  = (const float*)d_in[M[18]];
    const float* bnb  = (const float*)d_in[M[19]];
    const float* dsw  = (const float*)d_in[M[20]];
    const float* dsb  = (const float*)d_in[M[21]];
    float* out = (float*)d_out;

    int write_attw = (out_size >= 2048 + NB * NTCR) ? 1 : 0;

    dummyKernel<<<1, 32>>>();
    dummyKernel<<<1, 32>>>();
    prepKernel<<<6, 256>>>(cw0, cb0, cw1, cb1, cw2, cb2, cw3, cb3, cw4, cb4, cw5, cb5);
    convKernel<<<NBLK_CONV, CONV_THREADS>>>(x, fc1w, fc1b, waw);
    attnKernel<<<NB, 128>>>(dfw, dfb, out, write_attw);
    bnKernel<<<1, 1024>>>(bng, bnb, dsw, dsb, out);
}

// round 11
// speedup vs baseline: 1.4464x; 1.4464x over previous
#include <cuda_runtime.h>
#include <cstdint>

// Problem constants
#define NB    1024
#define NTCR  100
#define NFEAT 15
#define NAA   24
#define NCH   14          // total conv output channels
#define NINST (NB*NTCR)   // 102400
#define INST_PER_BLOCK 16
#define NBLK_CONV (NINST/INST_PER_BLOCK) // 6400
#define CONV_THREADS 224  // 7 warps: warp = height-balanced channel pair
#define XSTRIDE 371       // odd word stride -> conflict-free inst banks, room for tail reads
#define NWPACK 1484       // 1470 weights (layout [c][ch*7+t]) + 14 biases

// ---------------- scratch (static device memory; no allocation) ----------------
__device__ float g_hbuf[NINST * NCH];   // h vectors (per instance)
__device__ float g_sbuf[NINST];         // attention scores
__device__ float g_zbuf[NB * NCH];      // decoder_f output (pre-BN)
__device__ float g_wpack[NWPACK];       // staged conv weights+bias

// Diagnostic: keeps convKernel at ncu's captured launch index (-s 5 -c 1).
__global__ void dummyKernel() {}

// ---------------- prep: pack conv weights, layout [c][ch*7 + t] ----------------
__global__ void prepKernel(const float* __restrict__ w0, const float* __restrict__ b0,
                           const float* __restrict__ w1, const float* __restrict__ b1,
                           const float* __restrict__ w2, const float* __restrict__ b2,
                           const float* __restrict__ w3, const float* __restrict__ b3,
                           const float* __restrict__ w4, const float* __restrict__ b4,
                           const float* __restrict__ w5, const float* __restrict__ b5) {
    const int chH[14]    = {2,2,2,3,3,3,4,4,4,5,5,6,6,7};
    const int chF[14]    = {0,1,2,0,1,2,0,1,2,0,1,0,1,0};
    const int chConv[14] = {0,0,0,1,1,1,2,2,2,3,3,4,4,5};
    const float* cws[6] = {w0,w1,w2,w3,w4,w5};
    const float* cbs[6] = {b0,b1,b2,b3,b4,b5};
    int idx = blockIdx.x * blockDim.x + threadIdx.x;
    if (idx < 1470) {
        int c  = idx / 98;
        int r  = idx - c * 98;
        int ch = r / 7;
        int t  = r - ch * 7;
        int h  = chH[ch];
        float w = 0.0f;
        if (t < h) {
            const float* W = cws[chConv[ch]];
            w = W[(chF[ch] * NFEAT + c) * h + t];
        }
        g_wpack[idx] = w;
    } else if (idx < NWPACK) {
        int ch = idx - 1470;
        g_wpack[idx] = cbs[chConv[ch]][chF[ch]];
    }
}

// ---------------- conv body: compile-time heights, barrier-free mainloop ----------------
// lane owns (inst, half): positions p = half*12 + q, q in [0,12).
// Returns this lane's partial max for channels A (height H1) and B (H2);
// valid q bound for half=1 is 13-H (positions p <= 24-H). Tail x reads past the
// row land in smem padding: garbage feeds only excluded acc entries.
template<int H1, int H2>
__device__ __forceinline__ void convBody(const float* __restrict__ xt_lane,
                                         const float* __restrict__ wsm,
                                         int chA, int chB, int half,
                                         float& fA, float& fB) {
    constexpr int HM = (H1 > H2) ? H1 : H2;
    float accA[12], accB[12];
    #pragma unroll
    for (int q = 0; q < 12; ++q) { accA[q] = 0.0f; accB[q] = 0.0f; }

    #pragma unroll 1
    for (int c = 0; c < 15; ++c) {
        float xw[11 + HM];
        const float* xr = xt_lane + c * 24;
        #pragma unroll
        for (int u = 0; u < 11 + HM; ++u) xw[u] = xr[u];

        const float* wrA = wsm + c * 98 + chA * 7;
        #pragma unroll
        for (int t = 0; t < H1; ++t) {
            float wv = wrA[t];
            #pragma unroll
            for (int q = 0; q < 12; ++q)
                accA[q] = fmaf(wv, xw[q + t], accA[q]);
        }
        const float* wrB = wsm + c * 98 + chB * 7;
        #pragma unroll
        for (int t = 0; t < H2; ++t) {
            float wv = wrB[t];
            #pragma unroll
            for (int q = 0; q < 12; ++q)
                accB[q] = fmaf(wv, xw[q + t], accB[q]);
        }
    }

    // partial max with compile-time valid bounds (half=1 -> q < 13-H)
    float mA = accA[0];
    #pragma unroll
    for (int q = 1; q < 13 - H1; ++q) mA = fmaxf(mA, accA[q]);
    float mAf = mA;
    #pragma unroll
    for (int q = 13 - H1; q < 12; ++q) mAf = fmaxf(mAf, accA[q]);
    fA = half ? mA : mAf;

    float mB = accB[0];
    #pragma unroll
    for (int q = 1; q < 13 - H2; ++q) mB = fmaxf(mB, accB[q]);
    float mBf = mB;
    #pragma unroll
    for (int q = 13 - H2; q < 12; ++q) mBf = fmaxf(mBf, accB[q]);
    fB = half ? mB : mBf;
}

// ---------------- stage 1: conv + relu + maxpool + fc1 + relu + score ----------------
__global__ void __launch_bounds__(CONV_THREADS) convKernel(const float* __restrict__ x,
                                                           const float* __restrict__ fc1w,
                                                           const float* __restrict__ fc1b,
                                                           const float* __restrict__ waw) {
    __shared__ float xt[INST_PER_BLOCK * XSTRIDE]; // full x tile, staged ONCE
    __shared__ float wsm[1470];                    // [c][ch*7+t]
    __shared__ float fcw[224];                     // 16x14 zero-padded
    __shared__ float fcb[16];
    __shared__ float wav[16];
    __shared__ float wbias[16];
    __shared__ float feats[INST_PER_BLOCK][17];
    __shared__ float scs[INST_PER_BLOCK][14];

    int tid  = threadIdx.x;
    int w    = tid >> 5;      // 0..6 = channel pair
    int lane = tid & 31;
    int inst = lane & 15;
    int half = lane >> 4;
    int instBase = blockIdx.x * INST_PER_BLOCK;

    for (int i = tid; i < 1470; i += CONV_THREADS) wsm[i] = g_wpack[i];
    fcw[tid] = (tid < 196) ? fc1w[tid] : 0.0f;     // blockDim == 224 covers all
    if (tid < 16) {
        fcb[tid]   = (tid < 14) ? fc1b[tid] : 0.0f;
        wav[tid]   = (tid < 14) ? waw[tid]  : 0.0f;
        wbias[tid] = (tid < 14) ? g_wpack[1470 + tid] : 0.0f;
    }

    // stage the whole 16-instance x tile (coalesced global reads)
    for (int e = tid; e < INST_PER_BLOCK * 360; e += CONV_THREADS) {
        int ii = e / 360;
        int r  = e - ii * 360;
        xt[ii * XSTRIDE + r] = x[(size_t)(instBase + ii) * 360 + r];
    }
    __syncthreads();

    // height-balanced pairs: (13,0)=9 (11,1)=8 (12,2)=8 (9,3)=8 (10,4)=8 (6,5)=7 (7,8)=8
    const int pA[7] = {13, 11, 12,  9, 10,  6,  7};
    const int pB[7] = { 0,  1,  2,  3,  4,  5,  8};
    int chA = pA[w], chB = pB[w];

    const float* xt_lane = xt + inst * XSTRIDE + half * 12;

    float fA, fB;
    switch (w) {
        case 0:          convBody<7,2>(xt_lane, wsm, chA, chB, half, fA, fB); break;
        case 1: case 2:  convBody<6,2>(xt_lane, wsm, chA, chB, half, fA, fB); break;
        case 3: case 4:  convBody<5,3>(xt_lane, wsm, chA, chB, half, fA, fB); break;
        case 5:          convBody<4,3>(xt_lane, wsm, chA, chB, half, fA, fB); break;
        default:         convBody<4,4>(xt_lane, wsm, chA, chB, half, fA, fB); break;
    }

    // combine halves
    fA = fmaxf(fA, __shfl_xor_sync(0xffffffffu, fA, 16));
    fB = fmaxf(fB, __shfl_xor_sync(0xffffffffu, fB, 16));
    if (half == 0) {
        feats[inst][chA] = fmaxf(fA + wbias[chA], 0.0f);
        feats[inst][chB] = fmaxf(fB + wbias[chB], 0.0f);
    }
    __syncthreads();

    // fc1 + relu: 224 threads = 16 inst x 14 outputs, exact
    {
        int ii = tid / 14;
        int j  = tid - ii * 14;
        float hv = fcb[j];
        #pragma unroll
        for (int k = 0; k < 14; ++k)
            hv = fmaf(fcw[j * 14 + k], feats[ii][k], hv);
        hv = fmaxf(hv, 0.0f);
        g_hbuf[(size_t)(instBase + ii) * 14 + j] = hv;
        scs[ii][j] = hv * wav[j];
    }
    __syncthreads();

    if (tid < INST_PER_BLOCK) {
        float s = 0.0f;
        #pragma unroll
        for (int j = 0; j < 14; ++j) s += scs[tid][j];
        g_sbuf[instBase + tid] = s;
    }
}

// ---------------- stage 2: sparsemax + pooled + decoder_f (one block per repertoire) ----------------
__global__ void __launch_bounds__(128) attnKernel(const float* __restrict__ decfw,
                                                  const float* __restrict__ decfb,
                                                  float* __restrict__ out,
                                                  int write_attw) {
    __shared__ float z[100];
    __shared__ float zsrt[100];
    __shared__ float csh[100];
    __shared__ float aw[100];
    __shared__ float hsh[1400];
    __shared__ float pooled[14];
    __shared__ int   ks_sh;

    int b = blockIdx.x;
    int t = threadIdx.x;

    if (t == 0) ks_sh = 1;
    if (t < 100) z[t] = g_sbuf[b * 100 + t];
    for (int i = t; i < 1400; i += 128) hsh[i] = g_hbuf[b * 1400 + i];
    __syncthreads();

    // exact O(n^2) rank sort (descending, stable)
    if (t < 100) {
        float zi = z[t];
        int r = 0;
        for (int j2 = 0; j2 < 100; ++j2) {
            float zj = z[j2];
            r += (int)(zj > zi) | ((int)(zj == zi) & (int)(j2 < t));
        }
        zsrt[r] = zi;
    }
    __syncthreads();

    // parallel cumsum (triangular) + support-size via atomicMax
    if (t < 100) {
        float cs = 0.0f;
        for (int i2 = 0; i2 <= t; ++i2) cs += zsrt[i2];
        csh[t] = cs;
        if (1.0f + (float)(t + 1) * zsrt[t] > cs) atomicMax(&ks_sh, t + 1);
    }
    __syncthreads();

    int   ks  = ks_sh;
    float tau = (csh[ks - 1] - 1.0f) / (float)ks;

    if (t < 100) {
        float a = fmaxf(z[t] - tau, 0.0f);
        aw[t] = a;
        if (write_attw) out[2048 + b * 100 + t] = a;
    }
    __syncthreads();

    if (t < 14) {
        float acc = 0.0f;
        #pragma unroll 4
        for (int p = 0; p < 100; ++p)
            acc = fmaf(aw[p], hsh[p * 14 + t], acc);
        pooled[t] = acc;
    }
    __syncthreads();

    if (t < 14) {
        float zz = decfb[t];
        #pragma unroll
        for (int k = 0; k < 14; ++k) zz = fmaf(decfw[t * 14 + k], pooled[k], zz);
        g_zbuf[b * 14 + t] = zz;
    }
}

// ---------------- stage 3: batchnorm (batch stats) + relu + decoder_s ----------------
__global__ void __launch_bounds__(1024) bnKernel(const float* __restrict__ bng,
                                                 const float* __restrict__ bnb,
                                                 const float* __restrict__ dsw,
                                                 const float* __restrict__ dsb,
                                                 float* __restrict__ out) {
    __shared__ float ssum[32][14];
    __shared__ float ssq[32][14];
    __shared__ float mu[14];
    __shared__ float sc[14];

    int b    = threadIdx.x;
    int w    = b >> 5;
    int lane = b & 31;

    float zr[14];
    #pragma unroll
    for (int j = 0; j < 14; ++j) zr[j] = g_zbuf[b * 14 + j];

    #pragma unroll
    for (int j = 0; j < 14; ++j) {
        float s = zr[j];
        float q = zr[j] * zr[j];
        #pragma unroll
        for (int off = 16; off; off >>= 1) {
            s += __shfl_xor_sync(0xffffffffu, s, off);
            q += __shfl_xor_sync(0xffffffffu, q, off);
        }
        if (lane == 0) { ssum[w][j] = s; ssq[w][j] = q; }
    }
    __syncthreads();

    if (b < 14) {
        float s = 0.0f, q = 0.0f;
        #pragma unroll
        for (int i = 0; i < 32; ++i) { s += ssum[i][b]; q += ssq[i][b]; }
        float m = s * (1.0f / 1024.0f);
        float v = q * (1.0f / 1024.0f) - m * m;
        mu[b] = m;
        sc[b] = bng[b] * rsqrtf(v + 1e-5f);
    }
    __syncthreads();

    float l0 = dsb[0], l1 = dsb[1];
    #pragma unroll
    for (int j = 0; j < 14; ++j) {
        float zn = fmaxf((zr[j] - mu[j]) * sc[j] + bnb[j], 0.0f);
        l0 = fmaf(dsw[j],      zn, l0);
        l1 = fmaf(dsw[14 + j], zn, l1);
    }
    out[b * 2]     = l0;
    out[b * 2 + 1] = l1;
}

// ---------------- launch ----------------
extern "C" void kernel_launch(void* const* d_in, const int* in_sizes, int n_in,
                              void* d_out, int out_size) {
    static const int MAP_INS[22] = {0,1,2,3,4,5,6,7,8,9,10,11,12,13,14,15,16,17,18,19,20,21};
    //                       x  cw0 cb0 cw1 cb1 cw2 cb2 cw3 cb3 cw4 cb4 cw5 cb5 f1w f1b waw dfw dfb bng bnb dsw dsb
    static const int MAP_AL[22] = {21, 8,  2,  9,  3, 10,  4, 11,  5, 12,  6, 13,  7, 19, 18, 20, 15, 14,  1,  0, 17, 16};

    const int* M = MAP_INS;
    if (n_in >= 22 && in_sizes[0] != NINST * NFEAT * NAA && in_sizes[21] == NINST * NFEAT * NAA) {
        M = MAP_AL;
    }

    const float* x    = (const float*)d_in[M[0]];
    const float* cw0  = (const float*)d_in[M[1]];
    const float* cb0  = (const float*)d_in[M[2]];
    const float* cw1  = (const float*)d_in[M[3]];
    const float* cb1  = (const float*)d_in[M[4]];
    const float* cw2  = (const float*)d_in[M[5]];
    const float* cb2  = (const float*)d_in[M[6]];
    const float* cw3  = (const float*)d_in[M[7]];
    const float* cb3  = (const float*)d_in[M[8]];
    const float* cw4  = (const float*)d_in[M[9]];
    const float* cb4  = (const float*)d_in[M[10]];
    const float* cw5  = (const float*)d_in[M[11]];
    const float* cb5  = (const float*)d_in[M[12]];
    const float* fc1w = (const float*)d_in[M[13]];
    const float* fc1b = (const float*)d_in[M[14]];
    const float* waw  = (const float*)d_in[M[15]];
    const float* dfw  = (const float*)d_in[M[16]];
    const float* dfb  = (const float*)d_in[M[17]];
    const float* bng  = (const float*)d_in[M[18]];
    const float* bnb  = (const float*)d_in[M[19]];
    const float* dsw  = (const float*)d_in[M[20]];
    const float* dsb  = (const float*)d_in[M[21]];
    float* out = (float*)d_out;

    int write_attw = (out_size >= 2048 + NB * NTCR) ? 1 : 0;

    dummyKernel<<<1, 32>>>();
    dummyKernel<<<1, 32>>>();
    prepKernel<<<6, 256>>>(cw0, cb0, cw1, cb1, cw2, cb2, cw3, cb3, cw4, cb4, cw5, cb5);
    convKernel<<<NBLK_CONV, CONV_THREADS>>>(x, fc1w, fc1b, waw);
    attnKernel<<<NB, 128>>>(dfw, dfb, out, write_attw);
    bnKernel<<<1, 1024>>>(bng, bnb, dsw, dsb, out);
}

// round 12
// speedup vs baseline: 1.7227x; 1.1910x over previous
#include <cuda_runtime.h>
#include <cstdint>

// Problem constants
#define NB    1024
#define NTCR  100
#define NFEAT 15
#define NAA   24
#define NCH   14          // total conv output channels
#define NINST (NB*NTCR)   // 102400
#define INST_PER_BLOCK 32
#define NBLK_CONV (NINST/INST_PER_BLOCK) // 3200
#define CONV_THREADS 224  // 7 warps: warp = height-balanced channel pair, lane = instance
#define NWPACK 1484       // 1470 weights (layout [c][ch*7+t]) + 14 biases
#define XT_WORDS (360*33) // transposed x tile [r][inst], stride 33 -> conflict-free both ways

// ---------------- scratch (static device memory; no allocation) ----------------
__device__ float g_hbuf[NINST * NCH];   // h vectors (per instance)
__device__ float g_sbuf[NINST];         // attention scores
__device__ float g_zbuf[NB * NCH];      // decoder_f output (pre-BN)
__device__ float g_wpack[NWPACK];       // staged conv weights+bias

// Diagnostic: keeps convKernel at ncu's captured launch index (-s 5 -c 1).
__global__ void dummyKernel() {}

// ---------------- prep: pack conv weights, layout [c][ch*7 + t] ----------------
__global__ void prepKernel(const float* __restrict__ w0, const float* __restrict__ b0,
                           const float* __restrict__ w1, const float* __restrict__ b1,
                           const float* __restrict__ w2, const float* __restrict__ b2,
                           const float* __restrict__ w3, const float* __restrict__ b3,
                           const float* __restrict__ w4, const float* __restrict__ b4,
                           const float* __restrict__ w5, const float* __restrict__ b5) {
    const int chH[14]    = {2,2,2,3,3,3,4,4,4,5,5,6,6,7};
    const int chF[14]    = {0,1,2,0,1,2,0,1,2,0,1,0,1,0};
    const int chConv[14] = {0,0,0,1,1,1,2,2,2,3,3,4,4,5};
    const float* cws[6] = {w0,w1,w2,w3,w4,w5};
    const float* cbs[6] = {b0,b1,b2,b3,b4,b5};
    int idx = blockIdx.x * blockDim.x + threadIdx.x;
    if (idx < 1470) {
        int c  = idx / 98;
        int r  = idx - c * 98;
        int ch = r / 7;
        int t  = r - ch * 7;
        int h  = chH[ch];
        float w = 0.0f;
        if (t < h) {
            const float* W = cws[chConv[ch]];
            w = W[(chF[ch] * NFEAT + c) * h + t];
        }
        g_wpack[idx] = w;
    } else if (idx < NWPACK) {
        int ch = idx - 1470;
        g_wpack[idx] = cbs[chConv[ch]][chF[ch]];
    }
}

// ---------------- conv body: lane = instance, exact position counts ----------------
// xt_lane = xt + lane (word offset); x value (c,u) at xt_lane[(c*24+u)*33].
// Weights read via warp-uniform LDG broadcast from g_wpack.
template<int H1, int H2>
__device__ __forceinline__ void convBody(const float* __restrict__ xt_lane,
                                         const float* __restrict__ wA,
                                         const float* __restrict__ wB,
                                         float& fA, float& fB) {
    float accA[25 - H1];
    float accB[25 - H2];
    #pragma unroll
    for (int p = 0; p <= 24 - H1; ++p) accA[p] = 0.0f;
    #pragma unroll
    for (int p = 0; p <= 24 - H2; ++p) accB[p] = 0.0f;

    #pragma unroll 1
    for (int c = 0; c < 15; ++c) {
        float wtA[H1], wtB[H2];
        #pragma unroll
        for (int t = 0; t < H1; ++t) wtA[t] = wA[c * 98 + t];
        #pragma unroll
        for (int t = 0; t < H2; ++t) wtB[t] = wB[c * 98 + t];

        float xw[24];
        const float* xr = xt_lane + c * (24 * 33);
        #pragma unroll
        for (int u = 0; u < 24; ++u) xw[u] = xr[u * 33];

        #pragma unroll
        for (int t = 0; t < H1; ++t) {
            float wv = wtA[t];
            #pragma unroll
            for (int p = 0; p <= 24 - H1; ++p)
                accA[p] = fmaf(wv, xw[p + t], accA[p]);
        }
        #pragma unroll
        for (int t = 0; t < H2; ++t) {
            float wv = wtB[t];
            #pragma unroll
            for (int p = 0; p <= 24 - H2; ++p)
                accB[p] = fmaf(wv, xw[p + t], accB[p]);
        }
    }

    float mA = accA[0];
    #pragma unroll
    for (int p = 1; p <= 24 - H1; ++p) mA = fmaxf(mA, accA[p]);
    float mB = accB[0];
    #pragma unroll
    for (int p = 1; p <= 24 - H2; ++p) mB = fmaxf(mB, accB[p]);
    fA = mA;
    fB = mB;
}

// ---------------- stage 1: conv + relu + maxpool + fc1 + relu + score ----------------
__global__ void __launch_bounds__(CONV_THREADS, 3) convKernel(const float* __restrict__ x,
                                                              const float* __restrict__ fc1w,
                                                              const float* __restrict__ fc1b,
                                                              const float* __restrict__ waw) {
    __shared__ float xt[XT_WORDS];   // 47520B; feats/scs alias in after mainloop
    __shared__ float fcw[196];
    __shared__ float fcb[16];
    __shared__ float wav[16];
    __shared__ float wbias[16];

    int tid  = threadIdx.x;
    int w    = tid >> 5;      // 0..6 = channel pair
    int lane = tid & 31;      // instance within block
    int instBase = blockIdx.x * INST_PER_BLOCK;

    fcw[tid < 196 ? tid : 0] = fc1w[tid < 196 ? tid : 0];
    if (tid < 16) {
        fcb[tid]   = (tid < 14) ? fc1b[tid] : 0.0f;
        wav[tid]   = (tid < 14) ? waw[tid]  : 0.0f;
        wbias[tid] = (tid < 14) ? g_wpack[1470 + tid] : 0.0f;
    }

    // Fill transposed tile: global read COALESCED (e linear in x), STS conflict-free
    // (consecutive r -> +33 words -> +1 bank). Incremental wrap, no divisions.
    {
        const float* xg = x + (size_t)instBase * 360;
        int r = tid, inst = 0;
        for (int e = tid; e < INST_PER_BLOCK * 360; e += CONV_THREADS) {
            xt[r * 33 + inst] = xg[e];
            r += CONV_THREADS;
            if (r >= 360) { r -= 360; ++inst; }
        }
    }
    __syncthreads();

    // height-balanced pairs: (13,0)<7,2> (11,1)<6,2> (12,2)<6,2> (9,3)<5,3>
    //                        (10,4)<5,3> (6,5)<4,3> (7,8)<4,4>
    const int pA[7] = {13, 11, 12,  9, 10,  6,  7};
    const int pB[7] = { 0,  1,  2,  3,  4,  5,  8};
    int chA = pA[w], chB = pB[w];

    const float* xt_lane = xt + lane;
    const float* wA = g_wpack + chA * 7;
    const float* wB = g_wpack + chB * 7;

    float fA, fB;
    switch (w) {
        case 0:          convBody<7,2>(xt_lane, wA, wB, fA, fB); break;
        case 1: case 2:  convBody<6,2>(xt_lane, wA, wB, fA, fB); break;
        case 3: case 4:  convBody<5,3>(xt_lane, wA, wB, fA, fB); break;
        case 5:          convBody<4,3>(xt_lane, wA, wB, fA, fB); break;
        default:         convBody<4,4>(xt_lane, wA, wB, fA, fB); break;
    }

    // alias feats/scs into xt (all xt reads are done; barrier orders it)
    float* feats = xt;              // [32][17] -> 544 floats
    float* scs   = xt + 544;        // [32][14] -> 448 floats
    __syncthreads();

    feats[lane * 17 + chA] = fmaxf(fA + wbias[chA], 0.0f);
    feats[lane * 17 + chB] = fmaxf(fB + wbias[chB], 0.0f);
    __syncthreads();

    // fc1 + relu + score terms: 448 items over 224 threads
    for (int item = tid; item < INST_PER_BLOCK * 14; item += CONV_THREADS) {
        int ii = item / 14;
        int j  = item - ii * 14;
        float hv = fcb[j];
        #pragma unroll
        for (int k = 0; k < 14; ++k)
            hv = fmaf(fcw[j * 14 + k], feats[ii * 17 + k], hv);
        hv = fmaxf(hv, 0.0f);
        g_hbuf[(size_t)(instBase + ii) * 14 + j] = hv;
        scs[ii * 14 + j] = hv * wav[j];
    }
    __syncthreads();

    if (tid < INST_PER_BLOCK) {
        float s = 0.0f;
        #pragma unroll
        for (int j = 0; j < 14; ++j) s += scs[tid * 14 + j];
        g_sbuf[instBase + tid] = s;
    }
}

// ---------------- stage 2: sparsemax + pooled + decoder_f (one block per repertoire) ----------------
__global__ void __launch_bounds__(128) attnKernel(const float* __restrict__ decfw,
                                                  const float* __restrict__ decfb,
                                                  float* __restrict__ out,
                                                  int write_attw) {
    __shared__ float z[100];
    __shared__ float zsrt[100];
    __shared__ float csh[100];
    __shared__ float aw[100];
    __shared__ float hsh[1400];
    __shared__ float pooled[14];
    __shared__ int   ks_sh;

    int b = blockIdx.x;
    int t = threadIdx.x;

    if (t == 0) ks_sh = 1;
    if (t < 100) z[t] = g_sbuf[b * 100 + t];
    for (int i = t; i < 1400; i += 128) hsh[i] = g_hbuf[b * 1400 + i];
    __syncthreads();

    // exact O(n^2) rank sort (descending, stable)
    if (t < 100) {
        float zi = z[t];
        int r = 0;
        for (int j2 = 0; j2 < 100; ++j2) {
            float zj = z[j2];
            r += (int)(zj > zi) | ((int)(zj == zi) & (int)(j2 < t));
        }
        zsrt[r] = zi;
    }
    __syncthreads();

    // parallel cumsum (triangular) + support-size via atomicMax
    if (t < 100) {
        float cs = 0.0f;
        for (int i2 = 0; i2 <= t; ++i2) cs += zsrt[i2];
        csh[t] = cs;
        if (1.0f + (float)(t + 1) * zsrt[t] > cs) atomicMax(&ks_sh, t + 1);
    }
    __syncthreads();

    int   ks  = ks_sh;
    float tau = (csh[ks - 1] - 1.0f) / (float)ks;

    if (t < 100) {
        float a = fmaxf(z[t] - tau, 0.0f);
        aw[t] = a;
        if (write_attw) out[2048 + b * 100 + t] = a;
    }
    __syncthreads();

    if (t < 14) {
        float acc = 0.0f;
        #pragma unroll 4
        for (int p = 0; p < 100; ++p)
            acc = fmaf(aw[p], hsh[p * 14 + t], acc);
        pooled[t] = acc;
    }
    __syncthreads();

    if (t < 14) {
        float zz = decfb[t];
        #pragma unroll
        for (int k = 0; k < 14; ++k) zz = fmaf(decfw[t * 14 + k], pooled[k], zz);
        g_zbuf[b * 14 + t] = zz;
    }
}

// ---------------- stage 3: batchnorm (batch stats) + relu + decoder_s ----------------
__global__ void __launch_bounds__(1024) bnKernel(const float* __restrict__ bng,
                                                 const float* __restrict__ bnb,
                                                 const float* __restrict__ dsw,
                                                 const float* __restrict__ dsb,
                                                 float* __restrict__ out) {
    __shared__ float ssum[32][14];
    __shared__ float ssq[32][14];
    __shared__ float mu[14];
    __shared__ float sc[14];

    int b    = threadIdx.x;
    int w    = b >> 5;
    int lane = b & 31;

    float zr[14];
    #pragma unroll
    for (int j = 0; j < 14; ++j) zr[j] = g_zbuf[b * 14 + j];

    #pragma unroll
    for (int j = 0; j < 14; ++j) {
        float s = zr[j];
        float q = zr[j] * zr[j];
        #pragma unroll
        for (int off = 16; off; off >>= 1) {
            s += __shfl_xor_sync(0xffffffffu, s, off);
            q += __shfl_xor_sync(0xffffffffu, q, off);
        }
        if (lane == 0) { ssum[w][j] = s; ssq[w][j] = q; }
    }
    __syncthreads();

    if (b < 14) {
        float s = 0.0f, q = 0.0f;
        #pragma unroll
        for (int i = 0; i < 32; ++i) { s += ssum[i][b]; q += ssq[i][b]; }
        float m = s * (1.0f / 1024.0f);
        float v = q * (1.0f / 1024.0f) - m * m;
        mu[b] = m;
        sc[b] = bng[b] * rsqrtf(v + 1e-5f);
    }
    __syncthreads();

    float l0 = dsb[0], l1 = dsb[1];
    #pragma unroll
    for (int j = 0; j < 14; ++j) {
        float zn = fmaxf((zr[j] - mu[j]) * sc[j] + bnb[j], 0.0f);
        l0 = fmaf(dsw[j],      zn, l0);
        l1 = fmaf(dsw[14 + j], zn, l1);
    }
    out[b * 2]     = l0;
    out[b * 2 + 1] = l1;
}

// ---------------- launch ----------------
extern "C" void kernel_launch(void* const* d_in, const int* in_sizes, int n_in,
                              void* d_out, int out_size) {
    static const int MAP_INS[22] = {0,1,2,3,4,5,6,7,8,9,10,11,12,13,14,15,16,17,18,19,20,21};
    //                       x  cw0 cb0 cw1 cb1 cw2 cb2 cw3 cb3 cw4 cb4 cw5 cb5 f1w f1b waw dfw dfb bng bnb dsw dsb
    static const int MAP_AL[22] = {21, 8,  2,  9,  3, 10,  4, 11,  5, 12,  6, 13,  7, 19, 18, 20, 15, 14,  1,  0, 17, 16};

    const int* M = MAP_INS;
    if (n_in >= 22 && in_sizes[0] != NINST * NFEAT * NAA && in_sizes[21] == NINST * NFEAT * NAA) {
        M = MAP_AL;
    }

    const float* x    = (const float*)d_in[M[0]];
    const float* cw0  = (const float*)d_in[M[1]];
    const float* cb0  = (const float*)d_in[M[2]];
    const float* cw1  = (const float*)d_in[M[3]];
    const float* cb1  = (const float*)d_in[M[4]];
    const float* cw2  = (const float*)d_in[M[5]];
    const float* cb2  = (const float*)d_in[M[6]];
    const float* cw3  = (const float*)d_in[M[7]];
    const float* cb3  = (const float*)d_in[M[8]];
    const float* cw4  = (const float*)d_in[M[9]];
    const float* cb4  = (const float*)d_in[M[10]];
    const float* cw5  = (const float*)d_in[M[11]];
    const float* cb5  = (const float*)d_in[M[12]];
    const float* fc1w = (const float*)d_in[M[13]];
    const float* fc1b = (const float*)d_in[M[14]];
    const float* waw  = (const float*)d_in[M[15]];
    const float* dfw  = (const float*)d_in[M[16]];
    const float* dfb  = (const float*)d_in[M[17]];
    const float* bng  = (const float*)d_in[M[18]];
    const float* bnb  = (const float*)d_in[M[19]];
    const float* dsw  = (const float*)d_in[M[20]];
    const float* dsb  = (const float*)d_in[M[21]];
    float* out = (float*)d_out;

    int write_attw = (out_size >= 2048 + NB * NTCR) ? 1 : 0;

    dummyKernel<<<1, 32>>>();
    dummyKernel<<<1, 32>>>();
    prepKernel<<<6, 256>>>(cw0, cb0, cw1, cb1, cw2, cb2, cw3, cb3, cw4, cb4, cw5, cb5);
    convKernel<<<NBLK_CONV, CONV_THREADS>>>(x, fc1w, fc1b, waw);
    attnKernel<<<NB, 128>>>(dfw, dfb, out, write_attw);
    bnKernel<<<1, 1024>>>(bng, bnb, dsw, dsb, out);
}

// round 14
// speedup vs baseline: 1.8249x; 1.0593x over previous
#include <cuda_runtime.h>
#include <cstdint>

// Problem constants
#define NB    1024
#define NTCR  100
#define NFEAT 15
#define NAA   24
#define NCH   14          // total conv output channels
#define NINST (NB*NTCR)   // 102400
#define INSTB 64          // instances per block (32 f32x2 pairs)
#define NBLK_CONV (NINST/INSTB) // 1600
#define CONV_THREADS 224  // 7 warps: warp = height-balanced channel pair, lane = instance PAIR
#define XT_WORDS (360*66) // transposed x tile [r][inst], 64 inst + 2 pad -> conflict-free
#define XT_BYTES (XT_WORDS*4) // 95040 B dynamic smem

// ---------------- scratch (static device memory; no allocation) ----------------
__device__ float g_hbuf[NINST * NCH];           // h vectors (per instance)
__device__ float g_sbuf[NINST];                 // attention scores
__device__ float g_zbuf[NB * NCH];              // decoder_f output (pre-BN)
__device__ unsigned long long g_wpack2[1470];   // conv weights, duplicated f32x2 halves
__device__ float g_wbias[14];                   // conv biases

// Diagnostic: keeps convKernel at ncu's captured launch index (-s 5 -c 1).
__global__ void dummyKernel() {}

// ---------------- f32x2 helpers ----------------
__device__ __forceinline__ unsigned long long ffma2(unsigned long long a,
                                                    unsigned long long b,
                                                    unsigned long long c) {
    unsigned long long d;
    asm("fma.rn.f32x2 %0, %1, %2, %3;" : "=l"(d) : "l"(a), "l"(b), "l"(c));
    return d;
}
__device__ __forceinline__ float lo2(unsigned long long v) {
    return __uint_as_float((unsigned)(v & 0xffffffffull));
}
__device__ __forceinline__ float hi2(unsigned long long v) {
    return __uint_as_float((unsigned)(v >> 32));
}
// device-only (R13 compile fix: __float_as_uint is device-only)
__device__ __forceinline__ unsigned long long pack2h(float a, float b) {
    unsigned long long lo = __float_as_uint(a);
    unsigned long long hi = __float_as_uint(b);
    return (hi << 32) | lo;
}

// ---------------- prep: pack conv weights, layout [c][ch*7 + t], dup halves ----------------
__global__ void prepKernel(const float* __restrict__ w0, const float* __restrict__ b0,
                           const float* __restrict__ w1, const float* __restrict__ b1,
                           const float* __restrict__ w2, const float* __restrict__ b2,
                           const float* __restrict__ w3, const float* __restrict__ b3,
                           const float* __restrict__ w4, const float* __restrict__ b4,
                           const float* __restrict__ w5, const float* __restrict__ b5) {
    const int chH[14]    = {2,2,2,3,3,3,4,4,4,5,5,6,6,7};
    const int chF[14]    = {0,1,2,0,1,2,0,1,2,0,1,0,1,0};
    const int chConv[14] = {0,0,0,1,1,1,2,2,2,3,3,4,4,5};
    const float* cws[6] = {w0,w1,w2,w3,w4,w5};
    const float* cbs[6] = {b0,b1,b2,b3,b4,b5};
    int idx = blockIdx.x * blockDim.x + threadIdx.x;
    if (idx < 1470) {
        int c  = idx / 98;
        int r  = idx - c * 98;
        int ch = r / 7;
        int t  = r - ch * 7;
        int h  = chH[ch];
        float w = 0.0f;
        if (t < h) {
            const float* W = cws[chConv[ch]];
            w = W[(chF[ch] * NFEAT + c) * h + t];
        }
        g_wpack2[idx] = pack2h(w, w);
    } else if (idx < 1484) {
        int ch = idx - 1470;
        g_wbias[ch] = cbs[chConv[ch]][chF[ch]];
    }
}

// ---------------- conv body: lane = instance pair, streaming x, exact taps ----------------
// xv feeds every compile-time-valid (t, p=u-t) combination; acc arrays hold
// exactly the valid output positions. Weights via warp-uniform LDG.64 broadcast.
template<int H1, int H2>
__device__ __forceinline__ void convBody(const float* __restrict__ xt_lane,
                                         const unsigned long long* __restrict__ wA,
                                         const unsigned long long* __restrict__ wB,
                                         float& mAlo, float& mAhi,
                                         float& mBlo, float& mBhi) {
    unsigned long long accA[25 - H1];
    unsigned long long accB[25 - H2];
    #pragma unroll
    for (int p = 0; p <= 24 - H1; ++p) accA[p] = 0ull;
    #pragma unroll
    for (int p = 0; p <= 24 - H2; ++p) accB[p] = 0ull;

    #pragma unroll 1
    for (int c = 0; c < 15; ++c) {
        unsigned long long wtA[H1], wtB[H2];
        #pragma unroll
        for (int t = 0; t < H1; ++t) wtA[t] = wA[c * 98 + t];
        #pragma unroll
        for (int t = 0; t < H2; ++t) wtB[t] = wB[c * 98 + t];

        const float* xr = xt_lane + c * (24 * 66);
        #pragma unroll
        for (int u = 0; u < 24; ++u) {
            unsigned long long xv = *(const unsigned long long*)(xr + u * 66);
            #pragma unroll
            for (int t = 0; t < H1; ++t) {
                if (t <= u && (u - t) <= 24 - H1)
                    accA[u - t] = ffma2(wtA[t], xv, accA[u - t]);
            }
            #pragma unroll
            for (int t = 0; t < H2; ++t) {
                if (t <= u && (u - t) <= 24 - H2)
                    accB[u - t] = ffma2(wtB[t], xv, accB[u - t]);
            }
        }
    }

    float alo = lo2(accA[0]), ahi = hi2(accA[0]);
    #pragma unroll
    for (int p = 1; p <= 24 - H1; ++p) {
        alo = fmaxf(alo, lo2(accA[p]));
        ahi = fmaxf(ahi, hi2(accA[p]));
    }
    float blo = lo2(accB[0]), bhi = hi2(accB[0]);
    #pragma unroll
    for (int p = 1; p <= 24 - H2; ++p) {
        blo = fmaxf(blo, lo2(accB[p]));
        bhi = fmaxf(bhi, hi2(accB[p]));
    }
    mAlo = alo; mAhi = ahi; mBlo = blo; mBhi = bhi;
}

// ---------------- stage 1: conv + relu + maxpool + fc1 + relu + score ----------------
extern __shared__ float xt[];   // [360][66]: word r*66 + inst; pairs read LDS.64 at 2*pair

__global__ void __launch_bounds__(CONV_THREADS, 2) convKernel(const float* __restrict__ x,
                                                              const float* __restrict__ fc1w,
                                                              const float* __restrict__ fc1b,
                                                              const float* __restrict__ waw) {
    __shared__ float fcw[196];
    __shared__ float fcb[16];
    __shared__ float wav[16];
    __shared__ float wbias[16];

    int tid  = threadIdx.x;
    int w    = tid >> 5;      // 0..6 = channel pair
    int lane = tid & 31;      // instance pair within block
    int instBase = blockIdx.x * INSTB;

    for (int i = tid; i < 196; i += CONV_THREADS) fcw[i] = fc1w[i];
    if (tid < 16) {
        fcb[tid]   = (tid < 14) ? fc1b[tid] : 0.0f;
        wav[tid]   = (tid < 14) ? waw[tid]  : 0.0f;
        wbias[tid] = (tid < 14) ? g_wbias[tid] : 0.0f;
    }

    // Fill transposed tile: e = i*360 + r linear in x (coalesced LDG);
    // STS word r*66+i (2-way bank conflict on the fill only; mainloop is clean).
    {
        const float* xg = x + (size_t)instBase * 360;
        int r = tid, inst = 0;
        for (int e = tid; e < INSTB * 360; e += CONV_THREADS) {
            xt[r * 66 + inst] = xg[e];
            r += CONV_THREADS;
            if (r >= 360) { r -= 360; ++inst; }
        }
    }
    __syncthreads();

    // height-balanced pairs: (13,0)<7,2> (11,1)<6,2> (12,2)<6,2> (9,3)<5,3>
    //                        (10,4)<5,3> (6,5)<4,3> (7,8)<4,4>
    const int pA[7] = {13, 11, 12,  9, 10,  6,  7};
    const int pB[7] = { 0,  1,  2,  3,  4,  5,  8};
    int chA = pA[w], chB = pB[w];

    const float* xt_lane = xt + 2 * lane;
    const unsigned long long* wA = g_wpack2 + chA * 7;
    const unsigned long long* wB = g_wpack2 + chB * 7;

    float mAlo, mAhi, mBlo, mBhi;
    switch (w) {
        case 0:          convBody<7,2>(xt_lane, wA, wB, mAlo, mAhi, mBlo, mBhi); break;
        case 1: case 2:  convBody<6,2>(xt_lane, wA, wB, mAlo, mAhi, mBlo, mBhi); break;
        case 3: case 4:  convBody<5,3>(xt_lane, wA, wB, mAlo, mAhi, mBlo, mBhi); break;
        case 5:          convBody<4,3>(xt_lane, wA, wB, mAlo, mAhi, mBlo, mBhi); break;
        default:         convBody<4,4>(xt_lane, wA, wB, mAlo, mAhi, mBlo, mBhi); break;
    }

    // alias feats/scs into xt: barrier ensures ALL warps finished reading xt
    float* feats = xt;                      // [64][17]
    float* scs   = xt + INSTB * 17;         // [64][14]
    __syncthreads();

    {
        float bA = wbias[chA], bB = wbias[chB];
        feats[(2 * lane)     * 17 + chA] = fmaxf(mAlo + bA, 0.0f);
        feats[(2 * lane + 1) * 17 + chA] = fmaxf(mAhi + bA, 0.0f);
        feats[(2 * lane)     * 17 + chB] = fmaxf(mBlo + bB, 0.0f);
        feats[(2 * lane + 1) * 17 + chB] = fmaxf(mBhi + bB, 0.0f);
    }
    __syncthreads();

    // fc1 + relu + score terms: 64*14 = 896 items over 224 threads
    for (int item = tid; item < INSTB * 14; item += CONV_THREADS) {
        int ii = item / 14;
        int j  = item - ii * 14;
        float hv = fcb[j];
        #pragma unroll
        for (int k = 0; k < 14; ++k)
            hv = fmaf(fcw[j * 14 + k], feats[ii * 17 + k], hv);
        hv = fmaxf(hv, 0.0f);
        g_hbuf[(size_t)(instBase + ii) * 14 + j] = hv;
        scs[ii * 14 + j] = hv * wav[j];
    }
    __syncthreads();

    if (tid < INSTB) {
        float s = 0.0f;
        #pragma unroll
        for (int j = 0; j < 14; ++j) s += scs[tid * 14 + j];
        g_sbuf[instBase + tid] = s;
    }
}

// ---------------- stage 2: sparsemax + pooled + decoder_f (one block per repertoire) ----------------
__global__ void __launch_bounds__(128) attnKernel(const float* __restrict__ decfw,
                                                  const float* __restrict__ decfb,
                                                  float* __restrict__ out,
                                                  int write_attw) {
    __shared__ float z[100];
    __shared__ float zsrt[100];
    __shared__ float csh[100];
    __shared__ float aw[100];
    __shared__ float hsh[1400];
    __shared__ float pooled[14];
    __shared__ int   ks_sh;

    int b = blockIdx.x;
    int t = threadIdx.x;

    if (t == 0) ks_sh = 1;
    if (t < 100) z[t] = g_sbuf[b * 100 + t];
    for (int i = t; i < 1400; i += 128) hsh[i] = g_hbuf[b * 1400 + i];
    __syncthreads();

    // exact O(n^2) rank sort (descending, stable)
    if (t < 100) {
        float zi = z[t];
        int r = 0;
        for (int j2 = 0; j2 < 100; ++j2) {
            float zj = z[j2];
            r += (int)(zj > zi) | ((int)(zj == zi) & (int)(j2 < t));
        }
        zsrt[r] = zi;
    }
    __syncthreads();

    // parallel cumsum (triangular) + support-size via atomicMax
    if (t < 100) {
        float cs = 0.0f;
        for (int i2 = 0; i2 <= t; ++i2) cs += zsrt[i2];
        csh[t] = cs;
        if (1.0f + (float)(t + 1) * zsrt[t] > cs) atomicMax(&ks_sh, t + 1);
    }
    __syncthreads();

    int   ks  = ks_sh;
    float tau = (csh[ks - 1] - 1.0f) / (float)ks;

    if (t < 100) {
        float a = fmaxf(z[t] - tau, 0.0f);
        aw[t] = a;
        if (write_attw) out[2048 + b * 100 + t] = a;
    }
    __syncthreads();

    if (t < 14) {
        float acc = 0.0f;
        #pragma unroll 4
        for (int p = 0; p < 100; ++p)
            acc = fmaf(aw[p], hsh[p * 14 + t], acc);
        pooled[t] = acc;
    }
    __syncthreads();

    if (t < 14) {
        float zz = decfb[t];
        #pragma unroll
        for (int k = 0; k < 14; ++k) zz = fmaf(decfw[t * 14 + k], pooled[k], zz);
        g_zbuf[b * 14 + t] = zz;
    }
}

// ---------------- stage 3: batchnorm (batch stats) + relu + decoder_s ----------------
__global__ void __launch_bounds__(1024) bnKernel(const float* __restrict__ bng,
                                                 const float* __restrict__ bnb,
                                                 const float* __restrict__ dsw,
                                                 const float* __restrict__ dsb,
                                                 float* __restrict__ out) {
    __shared__ float ssum[32][14];
    __shared__ float ssq[32][14];
    __shared__ float mu[14];
    __shared__ float sc[14];

    int b    = threadIdx.x;
    int w    = b >> 5;
    int lane = b & 31;

    float zr[14];
    #pragma unroll
    for (int j = 0; j < 14; ++j) zr[j] = g_zbuf[b * 14 + j];

    #pragma unroll
    for (int j = 0; j < 14; ++j) {
        float s = zr[j];
        float q = zr[j] * zr[j];
        #pragma unroll
        for (int off = 16; off; off >>= 1) {
            s += __shfl_xor_sync(0xffffffffu, s, off);
            q += __shfl_xor_sync(0xffffffffu, q, off);
        }
        if (lane == 0) { ssum[w][j] = s; ssq[w][j] = q; }
    }
    __syncthreads();

    if (b < 14) {
        float s = 0.0f, q = 0.0f;
        #pragma unroll
        for (int i = 0; i < 32; ++i) { s += ssum[i][b]; q += ssq[i][b]; }
        float m = s * (1.0f / 1024.0f);
        float v = q * (1.0f / 1024.0f) - m * m;
        mu[b] = m;
        sc[b] = bng[b] * rsqrtf(v + 1e-5f);
    }
    __syncthreads();

    float l0 = dsb[0], l1 = dsb[1];
    #pragma unroll
    for (int j = 0; j < 14; ++j) {
        float zn = fmaxf((zr[j] - mu[j]) * sc[j] + bnb[j], 0.0f);
        l0 = fmaf(dsw[j],      zn, l0);
        l1 = fmaf(dsw[14 + j], zn, l1);
    }
    out[b * 2]     = l0;
    out[b * 2 + 1] = l1;
}

// ---------------- launch ----------------
extern "C" void kernel_launch(void* const* d_in, const int* in_sizes, int n_in,
                              void* d_out, int out_size) {
    static const int MAP_INS[22] = {0,1,2,3,4,5,6,7,8,9,10,11,12,13,14,15,16,17,18,19,20,21};
    //                       x  cw0 cb0 cw1 cb1 cw2 cb2 cw3 cb3 cw4 cb4 cw5 cb5 f1w f1b waw dfw dfb bng bnb dsw dsb
    static const int MAP_AL[22] = {21, 8,  2,  9,  3, 10,  4, 11,  5, 12,  6, 13,  7, 19, 18, 20, 15, 14,  1,  0, 17, 16};

    const int* M = MAP_INS;
    if (n_in >= 22 && in_sizes[0] != NINST * NFEAT * NAA && in_sizes[21] == NINST * NFEAT * NAA) {
        M = MAP_AL;
    }

    const float* x    = (const float*)d_in[M[0]];
    const float* cw0  = (const float*)d_in[M[1]];
    const float* cb0  = (const float*)d_in[M[2]];
    const float* cw1  = (const float*)d_in[M[3]];
    const float* cb1  = (const float*)d_in[M[4]];
    const float* cw2  = (const float*)d_in[M[5]];
    const float* cb2  = (const float*)d_in[M[6]];
    const float* cw3  = (const float*)d_in[M[7]];
    const float* cb3  = (const float*)d_in[M[8]];
    const float* cw4  = (const float*)d_in[M[9]];
    const float* cb4  = (const float*)d_in[M[10]];
    const float* cw5  = (const float*)d_in[M[11]];
    const float* cb5  = (const float*)d_in[M[12]];
    const float* fc1w = (const float*)d_in[M[13]];
    const float* fc1b = (const float*)d_in[M[14]];
    const float* waw  = (const float*)d_in[M[15]];
    const float* dfw  = (const float*)d_in[M[16]];
    const float* dfb  = (const float*)d_in[M[17]];
    const float* bng  = (const float*)d_in[M[18]];
    const float* bnb  = (const float*)d_in[M[19]];
    const float* dsw  = (const float*)d_in[M[20]];
    const float* dsb  = (const float*)d_in[M[21]];
    float* out = (float*)d_out;

    int write_attw = (out_size >= 2048 + NB * NTCR) ? 1 : 0;

    // opt-in to >48KB dynamic shared memory (idempotent, not an allocation)
    static int attr_done = 0;
    if (!attr_done) {
        cudaFuncSetAttribute(convKernel, cudaFuncAttributeMaxDynamicSharedMemorySize, XT_BYTES);
        attr_done = 1;
    }

    dummyKernel<<<1, 32>>>();
    dummyKernel<<<1, 32>>>();
    prepKernel<<<6, 256>>>(cw0, cb0, cw1, cb1, cw2, cb2, cw3, cb3, cw4, cb4, cw5, cb5);
    convKernel<<<NBLK_CONV, CONV_THREADS, XT_BYTES>>>(x, fc1w, fc1b, waw);
    attnKernel<<<NB, 128>>>(dfw, dfb, out, write_attw);
    bnKernel<<<1, 1024>>>(bng, bnb, dsw, dsb, out);
}